// round 5
// baseline (speedup 1.0000x reference)
#include <cuda_runtime.h>
#include <cuda_bf16.h>

// RFCM loss, fused single-pass formulation:
//   mem = y_pred^2
//   J1 total = sum_{b,k} (A - B^2/C),  A=Σ mem*img^2, B=Σ mem*img, C=Σ mem
//   J2 voxel = memΣ*boxΣ - memΣ^2 - Σ_k mem_k*box_k + Σ_k mem_k^2
//     (box = 3x3x3 ones incl. center, zero padding; nb = box - center)
//   out = ΣJ1/(B*N) + 8e-4 * ΣJ2/(B*N)

namespace {
constexpr int TX = 32, TY = 16, CZ = 16;
constexpr int PLW = TX + 2;          // 34
constexpr int PLSZ = PLW * (TY + 2); // 34*18 = 612
constexpr int NTH = TX * TY;         // 512
constexpr int GX = 128 / TX;         // 4
constexpr int GY = 128 / TY;         // 8
constexpr int GZ = (128 / CZ) * 2;   // 8 z-chunks * 2 batches = 16
constexpr int NBLK = GX * GY * GZ;   // 512
constexpr int NVOX = 128 * 128 * 128;
}

// Block partials: [NBLK][13] = A0..3, B0..3, C0..3, J2. Fully overwritten
// every launch -> no init kernel needed, deterministic (no atomics).
__device__ float g_part[NBLK * 13];

__global__ void __launch_bounds__(NTH, 2)
rfcm_main(const float* __restrict__ yp, const float* __restrict__ img) {
    __shared__ float sp[4][PLSZ];
    const int tx = threadIdx.x, ty = threadIdx.y;
    const int tid = ty * TX + tx;
    const int gx0 = blockIdx.x * TX, gy0 = blockIdx.y * TY;
    const int b  = blockIdx.z & 1;
    const int z0 = (int)(blockIdx.z >> 1) * CZ;

    const float* ypb = yp  + (size_t)b * 4 * NVOX;
    const float* imb = img + (size_t)b * NVOX;

    auto load_plane = [&](int zp) {
        const bool zin = ((unsigned)zp < 128u);
        #pragma unroll
        for (int i = 0; i < (4 * PLSZ + NTH - 1) / NTH; ++i) {
            int idx = tid + i * NTH;
            if (idx < 4 * PLSZ) {
                int k  = idx / PLSZ;
                int r  = idx - k * PLSZ;
                int ly = r / PLW;
                int lx = r - ly * PLW;
                int gy = gy0 + ly - 1, gx = gx0 + lx - 1;
                float v = 0.f;
                if (zin && (unsigned)gy < 128u && (unsigned)gx < 128u) {
                    float p = __ldg(ypb + (size_t)k * NVOX +
                                    (((size_t)zp * 128 + gy) * 128 + gx));
                    v = p * p;
                }
                sp[k][r] = v;
            }
        }
    };

    auto box2d = [&](int k) {  // 3x3 sum centered at this thread's voxel
        const float* s = &sp[k][ty * PLW + tx];
        return (s[0] + s[1] + s[2]) +
               (s[PLW] + s[PLW + 1] + s[PLW + 2]) +
               (s[2 * PLW] + s[2 * PLW + 1] + s[2 * PLW + 2]);
    };
    auto center = [&](int k) { return sp[k][(ty + 1) * PLW + (tx + 1)]; };

    float A[4] = {}, Bv[4] = {}, Cv[4] = {}, J2 = 0.f;
    float bprev[4], bcur[4], bnext[4], mcur[4], mnext[4];

    // prologue: plane z0-1 (2D box only), then plane z0 (box + center + ABC)
    load_plane(z0 - 1);
    __syncthreads();
    #pragma unroll
    for (int k = 0; k < 4; ++k) bprev[k] = box2d(k);
    __syncthreads();
    load_plane(z0);
    __syncthreads();
    #pragma unroll
    for (int k = 0; k < 4; ++k) { bcur[k] = box2d(k); mcur[k] = center(k); }
    {
        float im = imb[((size_t)z0 * 128 + (gy0 + ty)) * 128 + (gx0 + tx)];
        #pragma unroll
        for (int k = 0; k < 4; ++k) {
            Cv[k] += mcur[k]; Bv[k] += mcur[k] * im; A[k] += mcur[k] * im * im;
        }
    }

    for (int z = z0; z < z0 + CZ; ++z) {
        __syncthreads();           // everyone done reading sp before overwrite
        load_plane(z + 1);
        __syncthreads();
        #pragma unroll
        for (int k = 0; k < 4; ++k) { bnext[k] = box2d(k); mnext[k] = center(k); }
        if (z + 1 < z0 + CZ) {     // halo plane belongs to the next chunk
            float im = imb[((size_t)(z + 1) * 128 + (gy0 + ty)) * 128 + (gx0 + tx)];
            #pragma unroll
            for (int k = 0; k < 4; ++k) {
                Cv[k] += mnext[k]; Bv[k] += mnext[k] * im; A[k] += mnext[k] * im * im;
            }
        }
        // J2 at plane z
        float boxsum = 0.f, memsum = 0.f, t1 = 0.f, t2 = 0.f;
        #pragma unroll
        for (int k = 0; k < 4; ++k) {
            float b3 = bprev[k] + bcur[k] + bnext[k];
            boxsum += b3;
            memsum += mcur[k];
            t1 += mcur[k] * b3;
            t2 += mcur[k] * mcur[k];
        }
        J2 += memsum * boxsum - memsum * memsum - t1 + t2;
        #pragma unroll
        for (int k = 0; k < 4; ++k) { bprev[k] = bcur[k]; bcur[k] = bnext[k]; mcur[k] = mnext[k]; }
    }

    // ---- block reduction of 13 values (warp shuffle + smem across warps) ----
    float vals[13];
    #pragma unroll
    for (int k = 0; k < 4; ++k) { vals[k] = A[k]; vals[4 + k] = Bv[k]; vals[8 + k] = Cv[k]; }
    vals[12] = J2;
    #pragma unroll
    for (int off = 16; off; off >>= 1) {
        #pragma unroll
        for (int j = 0; j < 13; ++j)
            vals[j] += __shfl_down_sync(0xffffffffu, vals[j], off);
    }

    const int warp = tid >> 5, lane = tid & 31;
    __syncthreads();               // reuse sp as reduction scratch
    float* red = &sp[0][0];
    if (lane == 0) {
        #pragma unroll
        for (int j = 0; j < 13; ++j) red[warp * 13 + j] = vals[j];
    }
    __syncthreads();
    constexpr int NW = NTH / 32;   // 16 warps
    if (warp < 13) {
        float v = (lane < NW) ? red[lane * 13 + warp] : 0.f;
        #pragma unroll
        for (int off = 16; off; off >>= 1)
            v += __shfl_down_sync(0xffffffffu, v, off);
        if (lane == 0) {
            int blockid = blockIdx.x + GX * (blockIdx.y + GY * blockIdx.z);
            g_part[blockid * 13 + warp] = v;
        }
    }
}

__global__ void rfcm_final(float* __restrict__ out) {
    const int lane = threadIdx.x;  // 32 threads
    float acc[25];                 // A[2][4], B[2][4], C[2][4], J2
    #pragma unroll
    for (int i = 0; i < 25; ++i) acc[i] = 0.f;
    for (int e = lane; e < NBLK; e += 32) {
        // blockid = bx + 4*by + 32*bz, b = bz&1 -> b = (e>>5)&1
        int bb = (e >> 5) & 1;
        const float* p = &g_part[e * 13];
        #pragma unroll
        for (int k = 0; k < 4; ++k) {
            acc[bb * 4 + k]      += p[k];
            acc[8 + bb * 4 + k]  += p[4 + k];
            acc[16 + bb * 4 + k] += p[8 + k];
        }
        acc[24] += p[12];
    }
    #pragma unroll
    for (int off = 16; off; off >>= 1) {
        #pragma unroll
        for (int i = 0; i < 25; ++i)
            acc[i] += __shfl_down_sync(0xffffffffu, acc[i], off);
    }
    if (lane == 0) {
        float J1 = 0.f;
        #pragma unroll
        for (int i = 0; i < 8; ++i)
            J1 += acc[i] - acc[8 + i] * acc[8 + i] / acc[16 + i];
        const float inv = 1.0f / (2.0f * (float)NVOX);  // mean over B*N
        out[0] = J1 * inv + 0.0008f * (acc[24] * inv);
    }
}

extern "C" void kernel_launch(void* const* d_in, const int* in_sizes, int n_in,
                              void* d_out, int out_size) {
    const float* yp  = (const float*)d_in[0];  // y_pred [2,4,128,128,128] f32
    const float* img = (const float*)d_in[1];  // image  [2,1,128,128,128] f32
    float* out = (float*)d_out;                // scalar f32

    rfcm_main<<<dim3(GX, GY, GZ), dim3(TX, TY)>>>(yp, img);
    rfcm_final<<<1, 32>>>(out);
}

// round 7
// speedup vs baseline: 2.4684x; 2.4684x over previous
#include <cuda_runtime.h>
#include <cuda_bf16.h>

// RFCM loss, fused single-pass, separable formulation.
//   mem = y_pred^2
//   J1 total = sum_{b,k} (A - B^2/C),  A=Σ mem*img^2, B=Σ mem*img, C=Σ mem
//   J2 voxel = memΣ*boxΣ - memΣ^2 - Σ_k mem_k*box_k + Σ_k mem_k^2
//     (box = 3x3x3 ones incl. center, zero pad; nb = box - center)
//   out = (ΣJ1 + 8e-4 * ΣJ2) / (B*N)
//
// Layout: warp spans full x=128 (32 lanes x float4). Row sums (3-tap in x)
// via 2 shuffles; stored to smem; 3-tap in y via 3 LDS.128; 3-tap in z via
// register rolling. Double-buffered smem -> 1 barrier per plane.
// Deterministic last-block finalize (fixed summation order, no fp atomics).

namespace {
constexpr int TY   = 8;               // warps per block, one y-row each
constexpr int CZ   = 16;              // z-chunk per block
constexpr int NTH  = 32 * TY;         // 256
constexpr int NVOX = 128 * 128 * 128;
constexpr int GYB  = 128 / TY;        // 16
constexpr int GZB  = 128 / CZ;        // 8
constexpr int NBLK = GYB * GZB * 2;   // 256
}

__device__ float g_part[NBLK * 13];
__device__ unsigned int g_count;      // zero-init; reset by finalizer each launch

__device__ __forceinline__ float hsum4(float4 a) { return (a.x + a.y) + (a.z + a.w); }
__device__ __forceinline__ float dot4(float4 a, float4 b) {
    return fmaf(a.x, b.x, fmaf(a.y, b.y, fmaf(a.z, b.z, a.w * b.w)));
}
__device__ __forceinline__ float4 add4(float4 a, float4 b) {
    return make_float4(a.x + b.x, a.y + b.y, a.z + b.z, a.w + b.w);
}

__global__ void __launch_bounds__(NTH, 2)
rfcm(const float* __restrict__ yp, const float* __restrict__ img,
     float* __restrict__ out) {
    __shared__ float sb[2][4][TY + 2][128];   // rowsum planes, double-buffered
    const int lane = threadIdx.x, wy = threadIdx.y;
    const int tid  = wy * 32 + lane;
    const int gy0  = blockIdx.x * TY;
    const int z0   = blockIdx.y * CZ;
    const int b    = blockIdx.z;
    const int x0   = lane * 4;

    const float* ypb = yp  + (size_t)b * 4 * NVOX;
    const float* imb = img + (size_t)b * NVOX;

    auto loadsq = [&](int k, int zp, int y) -> float4 {
        float4 v = __ldg(reinterpret_cast<const float4*>(
            ypb + (size_t)k * NVOX + (((size_t)zp * 128 + y) * 128 + x0)));
        return make_float4(v.x * v.x, v.y * v.y, v.z * v.z, v.w * v.w);
    };
    auto rowsum = [&](float4 m) -> float4 {
        float left  = __shfl_up_sync(0xffffffffu, m.w, 1);
        float right = __shfl_down_sync(0xffffffffu, m.x, 1);
        if (lane == 0)  left  = 0.f;   // global x boundary (warp = full x)
        if (lane == 31) right = 0.f;
        return make_float4(left + m.x + m.y, m.x + m.y + m.z,
                           m.y + m.z + m.w, m.z + m.w + right);
    };

    // Load plane zp (squared), write rowsums to buffer par; return center-row m^2.
    auto process = [&](int zp, int par, float4 mout[4]) {
        const bool zin = ((unsigned)zp < 128u);
        const int yc = gy0 + wy;
        #pragma unroll
        for (int k = 0; k < 4; ++k) {
            float4 m = zin ? loadsq(k, zp, yc) : make_float4(0.f, 0.f, 0.f, 0.f);
            mout[k] = m;
            *reinterpret_cast<float4*>(&sb[par][k][wy + 1][x0]) = rowsum(m);
        }
        if (wy == 0 || wy == TY - 1) {        // y-halo rows (2 of 8 warps)
            const int r = (wy == 0) ? 0 : TY + 1;
            const int y = gy0 - 1 + r;
            const bool yin = ((unsigned)y < 128u);
            #pragma unroll
            for (int k = 0; k < 4; ++k) {
                float4 m = (zin && yin) ? loadsq(k, zp, y)
                                        : make_float4(0.f, 0.f, 0.f, 0.f);
                *reinterpret_cast<float4*>(&sb[par][k][r][x0]) = rowsum(m);
            }
        }
        __syncthreads();
    };
    auto colsum = [&](int par, float4 bout[4]) {   // 2D box = 3-row sum of rowsums
        #pragma unroll
        for (int k = 0; k < 4; ++k) {
            float4 r0 = *reinterpret_cast<const float4*>(&sb[par][k][wy][x0]);
            float4 r1 = *reinterpret_cast<const float4*>(&sb[par][k][wy + 1][x0]);
            float4 r2 = *reinterpret_cast<const float4*>(&sb[par][k][wy + 2][x0]);
            bout[k] = add4(add4(r0, r1), r2);
        }
    };

    float4 bprev[4], bcur[4], bnext[4], mcur[4], mnxt[4];
    float A[4] = {}, Bv[4] = {}, Cv[4] = {}, J2 = 0.f;

    auto accABC = [&](int zp, const float4 m[4]) {
        float4 iv = __ldg(reinterpret_cast<const float4*>(
            imb + (((size_t)zp * 128 + (gy0 + wy)) * 128 + x0)));
        float4 iv2 = make_float4(iv.x * iv.x, iv.y * iv.y, iv.z * iv.z, iv.w * iv.w);
        #pragma unroll
        for (int k = 0; k < 4; ++k) {
            Cv[k] += hsum4(m[k]);
            Bv[k] += dot4(m[k], iv);
            A[k]  += dot4(m[k], iv2);
        }
    };

    // prologue: plane z0-1 (2D box only), plane z0 (box + center + ABC)
    process(z0 - 1, 0, mnxt);
    colsum(0, bprev);
    process(z0, 1, mcur);
    colsum(1, bcur);
    accABC(z0, mcur);

    #pragma unroll 2
    for (int z = z0; z < z0 + CZ; ++z) {
        const int par = (z - z0) & 1;
        process(z + 1, par, mnxt);
        colsum(par, bnext);
        if (z + 1 < z0 + CZ) accABC(z + 1, mnxt);

        // J2 contribution at plane z (4 x-voxels vectorized)
        float4 ms = add4(add4(mcur[0], mcur[1]), add4(mcur[2], mcur[3]));
        float4 bs = make_float4(0.f, 0.f, 0.f, 0.f);
        float4 t1 = make_float4(0.f, 0.f, 0.f, 0.f);
        float4 t2 = make_float4(0.f, 0.f, 0.f, 0.f);
        #pragma unroll
        for (int k = 0; k < 4; ++k) {
            float4 b3 = add4(add4(bprev[k], bcur[k]), bnext[k]);
            bs = add4(bs, b3);
            t1.x = fmaf(mcur[k].x, b3.x, t1.x); t1.y = fmaf(mcur[k].y, b3.y, t1.y);
            t1.z = fmaf(mcur[k].z, b3.z, t1.z); t1.w = fmaf(mcur[k].w, b3.w, t1.w);
            t2.x = fmaf(mcur[k].x, mcur[k].x, t2.x); t2.y = fmaf(mcur[k].y, mcur[k].y, t2.y);
            t2.z = fmaf(mcur[k].z, mcur[k].z, t2.z); t2.w = fmaf(mcur[k].w, mcur[k].w, t2.w);
            bprev[k] = bcur[k]; bcur[k] = bnext[k];
        }
        float4 j2v = make_float4(ms.x * bs.x - ms.x * ms.x - t1.x + t2.x,
                                 ms.y * bs.y - ms.y * ms.y - t1.y + t2.y,
                                 ms.z * bs.z - ms.z * ms.z - t1.z + t2.z,
                                 ms.w * bs.w - ms.w * ms.w - t1.w + t2.w);
        J2 += hsum4(j2v);
        #pragma unroll
        for (int k = 0; k < 4; ++k) mcur[k] = mnxt[k];
    }

    // ---- block reduction: 13 scalars ----
    float vals[13];
    #pragma unroll
    for (int k = 0; k < 4; ++k) { vals[k] = A[k]; vals[4 + k] = Bv[k]; vals[8 + k] = Cv[k]; }
    vals[12] = J2;
    #pragma unroll
    for (int off = 16; off; off >>= 1)
        #pragma unroll
        for (int j = 0; j < 13; ++j)
            vals[j] += __shfl_down_sync(0xffffffffu, vals[j], off);

    __syncthreads();                         // done with stencil smem; reuse
    float* red = &sb[0][0][0][0];
    if (lane == 0) {
        #pragma unroll
        for (int j = 0; j < 13; ++j) red[wy * 13 + j] = vals[j];
    }
    __syncthreads();
    const int blockid = blockIdx.x + GYB * blockIdx.y + (GYB * GZB) * blockIdx.z;
    if (tid < 13) {
        float s = 0.f;
        #pragma unroll
        for (int w = 0; w < TY; ++w) s += red[w * 13 + tid];
        g_part[blockid * 13 + tid] = s;
    }

    // ---- deterministic last-block finalize ----
    __threadfence();
    __shared__ unsigned amLast;
    if (tid == 0) amLast = (atomicAdd(&g_count, 1u) == (unsigned)(NBLK - 1)) ? 1u : 0u;
    __syncthreads();
    if (amLast) {
        __threadfence();                     // acquire all g_part writes
        if (tid == 0) g_count = 0;           // reset for next launch (graph replay)
        // 256 threads, entry e = tid; entries 0..127 batch0, 128..255 batch1
        float v[13];
        const float* p = &g_part[tid * 13];
        #pragma unroll
        for (int j = 0; j < 13; ++j) v[j] = p[j];
        #pragma unroll
        for (int off = 16; off; off >>= 1)
            #pragma unroll
            for (int j = 0; j < 13; ++j)
                v[j] += __shfl_down_sync(0xffffffffu, v[j], off);
        if (lane == 0) {
            #pragma unroll
            for (int j = 0; j < 13; ++j) red[wy * 13 + j] = v[j];
        }
        __syncthreads();
        if (tid == 0) {
            float J1 = 0.f, J2t = 0.f;
            #pragma unroll
            for (int b2 = 0; b2 < 2; ++b2) {
                float s[13];
                #pragma unroll
                for (int j = 0; j < 13; ++j)
                    s[j] = red[(b2 * 4 + 0) * 13 + j] + red[(b2 * 4 + 1) * 13 + j] +
                           red[(b2 * 4 + 2) * 13 + j] + red[(b2 * 4 + 3) * 13 + j];
                #pragma unroll
                for (int k = 0; k < 4; ++k)
                    J1 += s[k] - s[4 + k] * s[4 + k] / s[8 + k];
                J2t += s[12];
            }
            out[0] = (J1 + 0.0008f * J2t) * (1.0f / (2.0f * (float)NVOX));
        }
    }
}

extern "C" void kernel_launch(void* const* d_in, const int* in_sizes, int n_in,
                              void* d_out, int out_size) {
    const float* yp  = (const float*)d_in[0];  // y_pred [2,4,128,128,128] f32
    const float* img = (const float*)d_in[1];  // image  [2,1,128,128,128] f32
    float* out = (float*)d_out;                // scalar f32

    rfcm<<<dim3(GYB, GZB, 2), dim3(32, TY)>>>(yp, img, out);
}

// round 9
// speedup vs baseline: 2.9494x; 1.1948x over previous
#include <cuda_runtime.h>
#include <cuda_bf16.h>

// RFCM loss, fused single-pass, separable + z-adjoint formulation.
//   mem = y_pred^2
//   J1 total = sum_{b,k} (A - B^2/C),  A=Σ mem*img^2, B=Σ mem*img, C=Σ mem
//   J2 = Σ_z [ Bsum(z)·M3S(z) − MS(z)² − Σ_k b_k(z)·m3_k(z) + Σ_k m_k(z)² ]
//     where b_k(z) = 2D 3x3 box of m_k at plane z, m3_k(z)=m_k(z−1)+m_k(z)+m_k(z+1)
//     (adjoint of the 3D box in z: Σ m·b3 == Σ b·m3 — only ONE box plane live)
//   out = (ΣJ1 + 8e-4 * ΣJ2) / (B*N)
//
// Warp spans full x=128 (32 lanes × float4): x 3-tap via 2 shuffles. Rowsums
// in double-buffered smem; y 3-tap via 3 LDS.128; z via m-register history.
// One-plane register prefetch hides L2/DRAM latency. Halo rows distributed:
// 2 rows × 4 clusters = 8 units = 8 warps → every warp loads 5 float4/plane,
// zero divergence. Deterministic last-block finalize.

namespace {
constexpr int TY   = 8;               // warps per block (one y-row each)
constexpr int CZ   = 16;              // z-chunk per block
constexpr int NTH  = 32 * TY;         // 256
constexpr int NVOX = 128 * 128 * 128;
constexpr int GYB  = 128 / TY;        // 16
constexpr int GZB  = 128 / CZ;        // 8
constexpr int NBLK = GYB * GZB * 2;   // 256
}

__device__ float g_part[NBLK * 13];
__device__ unsigned int g_count;      // zero-init; reset by finalizer each launch

__device__ __forceinline__ float hsum4(float4 a) { return (a.x + a.y) + (a.z + a.w); }
__device__ __forceinline__ float dot4(float4 a, float4 b) {
    return fmaf(a.x, b.x, fmaf(a.y, b.y, fmaf(a.z, b.z, a.w * b.w)));
}
__device__ __forceinline__ float4 add4(float4 a, float4 b) {
    return make_float4(a.x + b.x, a.y + b.y, a.z + b.z, a.w + b.w);
}
__device__ __forceinline__ float4 sq4(float4 a) {
    return make_float4(a.x * a.x, a.y * a.y, a.z * a.z, a.w * a.w);
}
__device__ __forceinline__ float4 zero4() { return make_float4(0.f, 0.f, 0.f, 0.f); }

__global__ void __launch_bounds__(NTH, 2)
rfcm(const float* __restrict__ yp, const float* __restrict__ img,
     float* __restrict__ out) {
    __shared__ float sb[2][4][TY + 2][128];   // rowsum planes, double-buffered
    const int lane = threadIdx.x, wy = threadIdx.y;
    const int tid  = wy * 32 + lane;
    const int gy0  = blockIdx.x * TY;
    const int z0   = blockIdx.y * CZ;
    const int b    = blockIdx.z;
    const int x0   = lane * 4;
    // Halo distribution: 2 rows × 4 clusters = 8 units, one per warp.
    const int  hk   = wy & 3;
    const int  hrow = (wy < 4) ? 0 : (TY + 1);
    const int  hy   = (wy < 4) ? (gy0 - 1) : (gy0 + TY);
    const bool hin  = ((unsigned)hy < 128u);

    const float* ypb = yp  + (size_t)b * 4 * NVOX;
    const float* imb = img + (size_t)b * NVOX;

    auto ld4 = [](const float* p) { return __ldg(reinterpret_cast<const float4*>(p)); };

    float4 rc[4], rh;                 // prefetched raw plane (center rows + halo unit)
    auto issue = [&](int zp) {
        const bool zin = ((unsigned)zp < 128u);
        const size_t pb = (size_t)zp * (128 * 128) + x0;
        #pragma unroll
        for (int k = 0; k < 4; ++k)
            rc[k] = zin ? ld4(ypb + (size_t)k * NVOX + pb + (size_t)(gy0 + wy) * 128)
                        : zero4();
        rh = (zin && hin) ? ld4(ypb + (size_t)hk * NVOX + pb + (size_t)hy * 128)
                          : zero4();
    };
    auto rowsum = [&](float4 m) {     // 3-tap in x via shuffles (warp = full row)
        float left  = __shfl_up_sync(0xffffffffu, m.w, 1);
        float right = __shfl_down_sync(0xffffffffu, m.x, 1);
        if (lane == 0)  left  = 0.f;
        if (lane == 31) right = 0.f;
        return make_float4(left + m.x + m.y, m.x + m.y + m.z,
                           m.y + m.z + m.w, m.z + m.w + right);
    };
    auto commit = [&](int par, float4 mnew[4]) {  // square + rowsum + store + 1 barrier
        #pragma unroll
        for (int k = 0; k < 4; ++k) {
            float4 m = sq4(rc[k]);
            mnew[k] = m;
            *reinterpret_cast<float4*>(&sb[par][k][wy + 1][x0]) = rowsum(m);
        }
        *reinterpret_cast<float4*>(&sb[par][hk][hrow][x0]) = rowsum(sq4(rh));
        __syncthreads();
    };
    auto colsum = [&](int par, float4 bo[4]) {    // 2D box = 3-row sum of rowsums
        #pragma unroll
        for (int k = 0; k < 4; ++k) {
            float4 r0 = *reinterpret_cast<const float4*>(&sb[par][k][wy][x0]);
            float4 r1 = *reinterpret_cast<const float4*>(&sb[par][k][wy + 1][x0]);
            float4 r2 = *reinterpret_cast<const float4*>(&sb[par][k][wy + 2][x0]);
            bo[k] = add4(add4(r0, r1), r2);
        }
    };

    float4 m1[4], m2[4], bprev[4];    // m(z-2), m(z-1), b(z-1)
    #pragma unroll
    for (int k = 0; k < 4; ++k) { m1[k] = zero4(); bprev[k] = zero4(); }
    float  A[4] = {}, Bv[4] = {}, Cv[4] = {};
    float4 J2v = zero4();

    // prologue: commit plane z0-1 (m only), prefetch plane z0 + img(z0)
    issue(z0 - 1);
    commit(0, m2);                    // m2 = m(z0-1); rc free again
    issue(z0);
    float4 imgc = ld4(imb + ((size_t)z0 * 128 + (gy0 + wy)) * 128 + x0);
    float4 imgn = zero4();

    #pragma unroll 2
    for (int i = 0; i <= CZ; ++i) {   // p = z0 + i : plane being committed
        const int  p       = z0 + i;
        const int  par     = (i + 1) & 1;
        const bool inchunk = (i < CZ);

        float4 mnew[4];
        commit(par, mnew);            // consume prefetched raw(p)
        if (i < CZ) issue(p + 1);     // prefetch raw(p+1); consumed next iter
        if (i < CZ - 1)
            imgn = ld4(imb + ((size_t)(p + 1) * 128 + (gy0 + wy)) * 128 + x0);

        if (inchunk) {                // ABC at plane p
            float4 iv = imgc, iv2 = sq4(imgc);
            #pragma unroll
            for (int k = 0; k < 4; ++k) {
                Cv[k] += hsum4(mnew[k]);
                Bv[k] += dot4(mnew[k], iv);
                A[k]  += dot4(mnew[k], iv2);
            }
        }
        if (i > 0) {                  // J2 at z = p-1 (uses bprev, m1, m2, mnew)
            float4 M3S = zero4(), BS = zero4(), MS2 = zero4();
            float4 t1 = zero4(), t2 = zero4();
            #pragma unroll
            for (int k = 0; k < 4; ++k) {
                float4 m3 = add4(add4(m1[k], m2[k]), mnew[k]);
                M3S = add4(M3S, m3);
                BS  = add4(BS, bprev[k]);
                MS2 = add4(MS2, m2[k]);
                t1.x = fmaf(bprev[k].x, m3.x, t1.x); t1.y = fmaf(bprev[k].y, m3.y, t1.y);
                t1.z = fmaf(bprev[k].z, m3.z, t1.z); t1.w = fmaf(bprev[k].w, m3.w, t1.w);
                t2.x = fmaf(m2[k].x, m2[k].x, t2.x); t2.y = fmaf(m2[k].y, m2[k].y, t2.y);
                t2.z = fmaf(m2[k].z, m2[k].z, t2.z); t2.w = fmaf(m2[k].w, m2[k].w, t2.w);
            }
            J2v.x += BS.x * M3S.x - MS2.x * MS2.x - t1.x + t2.x;
            J2v.y += BS.y * M3S.y - MS2.y * MS2.y - t1.y + t2.y;
            J2v.z += BS.z * M3S.z - MS2.z * MS2.z - t1.z + t2.z;
            J2v.w += BS.w * M3S.w - MS2.w * MS2.w - t1.w + t2.w;
        }
        if (inchunk) colsum(par, bprev);   // b(p) overwrites bprev in place
        #pragma unroll
        for (int k = 0; k < 4; ++k) { m1[k] = m2[k]; m2[k] = mnew[k]; }
        imgc = imgn;
    }

    // ---- block reduction: 13 scalars ----
    float vals[13];
    #pragma unroll
    for (int k = 0; k < 4; ++k) { vals[k] = A[k]; vals[4 + k] = Bv[k]; vals[8 + k] = Cv[k]; }
    vals[12] = hsum4(J2v);
    #pragma unroll
    for (int off = 16; off; off >>= 1)
        #pragma unroll
        for (int j = 0; j < 13; ++j)
            vals[j] += __shfl_down_sync(0xffffffffu, vals[j], off);

    __syncthreads();                       // stencil smem done; reuse as scratch
    float* red = &sb[0][0][0][0];
    if (lane == 0) {
        #pragma unroll
        for (int j = 0; j < 13; ++j) red[wy * 13 + j] = vals[j];
    }
    __syncthreads();
    const int blockid = blockIdx.x + GYB * blockIdx.y + (GYB * GZB) * blockIdx.z;
    if (tid < 13) {
        float s = 0.f;
        #pragma unroll
        for (int w = 0; w < TY; ++w) s += red[w * 13 + tid];
        g_part[blockid * 13 + tid] = s;
    }

    // ---- deterministic last-block finalize ----
    __threadfence();
    __shared__ unsigned amLast;
    if (tid == 0) amLast = (atomicAdd(&g_count, 1u) == (unsigned)(NBLK - 1)) ? 1u : 0u;
    __syncthreads();
    if (amLast) {
        __threadfence();                   // acquire all g_part writes
        if (tid == 0) g_count = 0;         // reset for next graph replay
        float v[13];                       // entry e = tid; 0..127 b0, 128..255 b1
        const float* p = &g_part[tid * 13];
        #pragma unroll
        for (int j = 0; j < 13; ++j) v[j] = p[j];
        #pragma unroll
        for (int off = 16; off; off >>= 1)
            #pragma unroll
            for (int j = 0; j < 13; ++j)
                v[j] += __shfl_down_sync(0xffffffffu, v[j], off);
        if (lane == 0) {
            #pragma unroll
            for (int j = 0; j < 13; ++j) red[wy * 13 + j] = v[j];
        }
        __syncthreads();
        if (tid == 0) {
            float J1 = 0.f, J2t = 0.f;
            #pragma unroll
            for (int b2 = 0; b2 < 2; ++b2) {
                float s[13];
                #pragma unroll
                for (int j = 0; j < 13; ++j)
                    s[j] = red[(b2 * 4 + 0) * 13 + j] + red[(b2 * 4 + 1) * 13 + j] +
                           red[(b2 * 4 + 2) * 13 + j] + red[(b2 * 4 + 3) * 13 + j];
                #pragma unroll
                for (int k = 0; k < 4; ++k)
                    J1 += s[k] - s[4 + k] * s[4 + k] / s[8 + k];
                J2t += s[12];
            }
            out[0] = (J1 + 0.0008f * J2t) * (1.0f / (2.0f * (float)NVOX));
        }
    }
}

extern "C" void kernel_launch(void* const* d_in, const int* in_sizes, int n_in,
                              void* d_out, int out_size) {
    const float* yp  = (const float*)d_in[0];  // y_pred [2,4,128,128,128] f32
    const float* img = (const float*)d_in[1];  // image  [2,1,128,128,128] f32
    float* out = (float*)d_out;                // scalar f32

    rfcm<<<dim3(GYB, GZB, 2), dim3(32, TY)>>>(yp, img, out);
}

// round 10
// speedup vs baseline: 3.7751x; 1.2800x over previous
#include <cuda_runtime.h>
#include <cuda_bf16.h>

// RFCM loss, fused single-pass, separable + z-adjoint formulation, f32x2 packed.
//   mem = y_pred^2
//   J1 total = sum_{b,k} (A - B^2/C),  A=Σ mem*img^2, B=Σ mem*img, C=Σ mem
//   J2 = Σ_z [ BS(z)·M3S(z) − MS(z)² − Σ_k b_k(z)·m3_k(z) + Σ_k m_k(z)² ]
//     b_k = 2D 3x3 box at plane z, m3_k(z) = m_k(z−1)+m_k(z)+m_k(z+1)
//   out = (ΣJ1 + 8e-4·ΣJ2) / (B*N)
//
// Warp = full x row (32 lanes × float4); x 3-tap via shuffles. Rowsums in
// double-buffered smem, y 3-tap via LDS.128, z via register history.
// One-plane prefetch. Elementwise math in packed f32x2 (FFMA2) — ptxas never
// emits these from C++, so inline PTX. z-loop fully unrolled: rolls renamed,
// plane addressing folded to immediate offsets. Deterministic last-block
// finalize.

namespace {
constexpr int TY   = 8;
constexpr int CZ   = 16;
constexpr int NTH  = 32 * TY;         // 256
constexpr int NVOX = 128 * 128 * 128;
constexpr int PL   = 128 * 128;       // z-plane stride (floats)
constexpr int GYB  = 128 / TY;        // 16
constexpr int GZB  = 128 / CZ;        // 8
constexpr int NBLK = GYB * GZB * 2;   // 256
}

__device__ float g_part[NBLK * 13];
__device__ unsigned int g_count;      // zero-init; reset by finalizer each launch

// ---- packed f32x2 helpers (sm_103a FFMA2 path; PTX-only) ----
struct P2 { unsigned long long v; };
struct Q  { P2 a, b; };               // a = lanes (0,1), b = lanes (2,3)

__device__ __forceinline__ P2 pk(float lo, float hi) {
    P2 r; asm("mov.b64 %0, {%1, %2};" : "=l"(r.v) : "f"(lo), "f"(hi)); return r;
}
__device__ __forceinline__ void upk(P2 a, float& lo, float& hi) {
    asm("mov.b64 {%0, %1}, %2;" : "=f"(lo), "=f"(hi) : "l"(a.v));
}
__device__ __forceinline__ P2 padd(P2 a, P2 b) {
    P2 r; asm("add.rn.f32x2 %0, %1, %2;" : "=l"(r.v) : "l"(a.v), "l"(b.v)); return r;
}
__device__ __forceinline__ P2 pmul(P2 a, P2 b) {
    P2 r; asm("mul.rn.f32x2 %0, %1, %2;" : "=l"(r.v) : "l"(a.v), "l"(b.v)); return r;
}
__device__ __forceinline__ P2 pfma(P2 a, P2 b, P2 c) {
    P2 r; asm("fma.rn.f32x2 %0, %1, %2, %3;"
              : "=l"(r.v) : "l"(a.v), "l"(b.v), "l"(c.v)); return r;
}
__device__ __forceinline__ P2 pneg(P2 a) {
    P2 r; asm("xor.b64 %0, %1, 0x8000000080000000;" : "=l"(r.v) : "l"(a.v)); return r;
}
__device__ __forceinline__ P2 pzero() { P2 r; r.v = 0ull; return r; }
__device__ __forceinline__ float psum(P2 a) { float lo, hi; upk(a, lo, hi); return lo + hi; }
__device__ __forceinline__ P2 u2a(ulonglong2 u) { P2 r; r.v = u.x; return r; }
__device__ __forceinline__ P2 u2b(ulonglong2 u) { P2 r; r.v = u.y; return r; }

__global__ void __launch_bounds__(NTH, 2)
rfcm(const float* __restrict__ yp, const float* __restrict__ img,
     float* __restrict__ out) {
    __shared__ __align__(16) float sb[2][4][TY + 2][128];  // rowsum planes, 2-buf
    const int lane = threadIdx.x, wy = threadIdx.y;
    const int tid  = wy * 32 + lane;
    const int gy0  = blockIdx.x * TY;
    const int z0   = blockIdx.y * CZ;
    const int b    = blockIdx.z;
    const int x0   = lane * 4;
    // halo: 2 rows × 4 clusters = 8 units, one per warp → zero divergence
    const int  hk   = wy & 3;
    const int  hrow = (wy < 4) ? 0 : (TY + 1);
    const int  hy   = (wy < 4) ? (gy0 - 1) : (gy0 + TY);
    const bool hin  = ((unsigned)hy < 128u);

    const float* ypb = yp  + (size_t)b * 4 * NVOX;
    // base pointers (z folded in as immediate offsets after full unroll)
    const float* pc[4];
    #pragma unroll
    for (int k = 0; k < 4; ++k)
        pc[k] = ypb + (size_t)k * NVOX + (size_t)(gy0 + wy) * 128 + x0;
    const float* ph  = ypb + (size_t)hk * NVOX + (size_t)(hin ? hy : 0) * 128 + x0;
    const float* pim = img + (size_t)b * NVOX + (size_t)(gy0 + wy) * 128 + x0;

    float4 rc[4], rh;                 // prefetched raw plane
    auto issue = [&](int zp) {
        const bool zin = ((unsigned)zp < 128u);
        const float4 z4 = make_float4(0.f, 0.f, 0.f, 0.f);
        #pragma unroll
        for (int k = 0; k < 4; ++k)
            rc[k] = zin ? __ldg(reinterpret_cast<const float4*>(pc[k] + (size_t)zp * PL)) : z4;
        rh = (zin && hin) ? __ldg(reinterpret_cast<const float4*>(ph + (size_t)zp * PL)) : z4;
    };
    auto ldimg = [&](int zp) -> Q {
        ulonglong2 u = __ldg(reinterpret_cast<const ulonglong2*>(pim + (size_t)zp * PL));
        Q q; q.a = u2a(u); q.b = u2b(u); return q;
    };
    auto rowsum_store = [&](int par, int k, int row,
                            float x, float y, float z, float w) {
        float left  = __shfl_up_sync(0xffffffffu, w, 1);
        float right = __shfl_down_sync(0xffffffffu, x, 1);
        if (lane == 0)  left  = 0.f;
        if (lane == 31) right = 0.f;
        float t1 = x + y, t2 = z + w;
        *reinterpret_cast<float4*>(&sb[par][k][row][x0]) =
            make_float4(left + t1, t1 + z, y + t2, t2 + right);
    };
    auto commit = [&](int par, Q mnew[4]) {     // square + rowsum + store + 1 bar
        #pragma unroll
        for (int k = 0; k < 4; ++k) {
            float x = rc[k].x * rc[k].x, y = rc[k].y * rc[k].y;
            float z = rc[k].z * rc[k].z, w = rc[k].w * rc[k].w;
            rowsum_store(par, k, wy + 1, x, y, z, w);
            mnew[k].a = pk(x, y); mnew[k].b = pk(z, w);
        }
        rowsum_store(par, hk, hrow, rh.x * rh.x, rh.y * rh.y,
                     rh.z * rh.z, rh.w * rh.w);
        __syncthreads();
    };
    auto colsum = [&](int par, Q bo[4]) {       // 2D box = 3-row sum of rowsums
        #pragma unroll
        for (int k = 0; k < 4; ++k) {
            ulonglong2 r0 = *reinterpret_cast<const ulonglong2*>(&sb[par][k][wy][x0]);
            ulonglong2 r1 = *reinterpret_cast<const ulonglong2*>(&sb[par][k][wy + 1][x0]);
            ulonglong2 r2 = *reinterpret_cast<const ulonglong2*>(&sb[par][k][wy + 2][x0]);
            bo[k].a = padd(padd(u2a(r0), u2a(r1)), u2a(r2));
            bo[k].b = padd(padd(u2b(r0), u2b(r1)), u2b(r2));
        }
    };

    Q m1[4], m2[4], bprev[4];
    #pragma unroll
    for (int k = 0; k < 4; ++k) {
        m1[k].a = pzero(); m1[k].b = pzero();
        bprev[k].a = pzero(); bprev[k].b = pzero();
    }
    P2 A2[4], B2[4], C2[4];
    #pragma unroll
    for (int k = 0; k < 4; ++k) { A2[k] = pzero(); B2[k] = pzero(); C2[k] = pzero(); }
    P2 j2a = pzero(), j2b = pzero();

    // prologue: commit plane z0-1 (m only), prefetch plane z0 + img(z0)
    issue(z0 - 1);
    commit(0, m2);                    // m2 = m(z0-1)
    issue(z0);
    Q imgc = ldimg(z0);
    Q imgn; imgn.a = pzero(); imgn.b = pzero();

    #pragma unroll
    for (int i = 0; i <= CZ; ++i) {   // p = z0 + i : plane being committed
        const int p   = z0 + i;
        const int par = (i + 1) & 1;

        Q mnew[4];
        commit(par, mnew);            // consume prefetched raw(p)
        if (i < CZ) issue(p + 1);
        if (i < CZ - 1) imgn = ldimg(p + 1);

        if (i < CZ) {                 // ABC at plane p
            P2 i2a = pmul(imgc.a, imgc.a), i2b = pmul(imgc.b, imgc.b);
            #pragma unroll
            for (int k = 0; k < 4; ++k) {
                C2[k] = padd(C2[k], padd(mnew[k].a, mnew[k].b));
                B2[k] = pfma(mnew[k].a, imgc.a, pfma(mnew[k].b, imgc.b, B2[k]));
                A2[k] = pfma(mnew[k].a, i2a,    pfma(mnew[k].b, i2b,    A2[k]));
            }
        }
        if (i > 0) {                  // J2 at z = p-1 (bprev=b(p-1), m2=m(p-1))
            P2 M3a = pzero(), M3b = pzero(), BSa = pzero(), BSb = pzero();
            P2 MSa = pzero(), MSb = pzero();
            P2 t1a = pzero(), t1b = pzero(), t2a = pzero(), t2b = pzero();
            #pragma unroll
            for (int k = 0; k < 4; ++k) {
                P2 m3a = padd(padd(m1[k].a, m2[k].a), mnew[k].a);
                P2 m3b = padd(padd(m1[k].b, m2[k].b), mnew[k].b);
                M3a = padd(M3a, m3a);          M3b = padd(M3b, m3b);
                BSa = padd(BSa, bprev[k].a);   BSb = padd(BSb, bprev[k].b);
                MSa = padd(MSa, m2[k].a);      MSb = padd(MSb, m2[k].b);
                t1a = pfma(bprev[k].a, m3a, t1a); t1b = pfma(bprev[k].b, m3b, t1b);
                t2a = pfma(m2[k].a, m2[k].a, t2a); t2b = pfma(m2[k].b, m2[k].b, t2b);
            }
            j2a = pfma(BSa, M3a, j2a); j2a = pfma(pneg(MSa), MSa, j2a);
            j2a = padd(j2a, padd(t2a, pneg(t1a)));
            j2b = pfma(BSb, M3b, j2b); j2b = pfma(pneg(MSb), MSb, j2b);
            j2b = padd(j2b, padd(t2b, pneg(t1b)));
        }
        if (i < CZ) colsum(par, bprev);        // b(p) overwrites bprev
        #pragma unroll
        for (int k = 0; k < 4; ++k) { m1[k] = m2[k]; m2[k] = mnew[k]; }
        imgc = imgn;
    }

    // ---- block reduction: 13 scalars ----
    float vals[13];
    #pragma unroll
    for (int k = 0; k < 4; ++k) {
        vals[k]     = psum(A2[k]);
        vals[4 + k] = psum(B2[k]);
        vals[8 + k] = psum(C2[k]);
    }
    vals[12] = psum(j2a) + psum(j2b);
    #pragma unroll
    for (int off = 16; off; off >>= 1)
        #pragma unroll
        for (int j = 0; j < 13; ++j)
            vals[j] += __shfl_down_sync(0xffffffffu, vals[j], off);

    __syncthreads();                       // stencil smem done; reuse as scratch
    float* red = &sb[0][0][0][0];
    if (lane == 0) {
        #pragma unroll
        for (int j = 0; j < 13; ++j) red[wy * 13 + j] = vals[j];
    }
    __syncthreads();
    const int blockid = blockIdx.x + GYB * blockIdx.y + (GYB * GZB) * blockIdx.z;
    if (tid < 13) {
        float s = 0.f;
        #pragma unroll
        for (int w = 0; w < TY; ++w) s += red[w * 13 + tid];
        g_part[blockid * 13 + tid] = s;
    }

    // ---- deterministic last-block finalize ----
    __threadfence();
    __shared__ unsigned amLast;
    if (tid == 0) amLast = (atomicAdd(&g_count, 1u) == (unsigned)(NBLK - 1)) ? 1u : 0u;
    __syncthreads();
    if (amLast) {
        __threadfence();                   // acquire all g_part writes
        if (tid == 0) g_count = 0;         // reset for next graph replay
        float v[13];                       // entry e = tid; 0..127 b0, 128..255 b1
        const float* pp = &g_part[tid * 13];
        #pragma unroll
        for (int j = 0; j < 13; ++j) v[j] = pp[j];
        #pragma unroll
        for (int off = 16; off; off >>= 1)
            #pragma unroll
            for (int j = 0; j < 13; ++j)
                v[j] += __shfl_down_sync(0xffffffffu, v[j], off);
        if (lane == 0) {
            #pragma unroll
            for (int j = 0; j < 13; ++j) red[wy * 13 + j] = v[j];
        }
        __syncthreads();
        if (tid == 0) {
            float J1 = 0.f, J2t = 0.f;
            #pragma unroll
            for (int b2 = 0; b2 < 2; ++b2) {
                float s[13];
                #pragma unroll
                for (int j = 0; j < 13; ++j)
                    s[j] = red[(b2 * 4 + 0) * 13 + j] + red[(b2 * 4 + 1) * 13 + j] +
                           red[(b2 * 4 + 2) * 13 + j] + red[(b2 * 4 + 3) * 13 + j];
                #pragma unroll
                for (int k = 0; k < 4; ++k)
                    J1 += s[k] - s[4 + k] * s[4 + k] / s[8 + k];
                J2t += s[12];
            }
            out[0] = (J1 + 0.0008f * J2t) * (1.0f / (2.0f * (float)NVOX));
        }
    }
}

extern "C" void kernel_launch(void* const* d_in, const int* in_sizes, int n_in,
                              void* d_out, int out_size) {
    const float* yp  = (const float*)d_in[0];  // y_pred [2,4,128,128,128] f32
    const float* img = (const float*)d_in[1];  // image  [2,1,128,128,128] f32
    float* out = (float*)d_out;                // scalar f32

    rfcm<<<dim3(GYB, GZB, 2), dim3(32, TY)>>>(yp, img, out);
}